// round 1
// baseline (speedup 1.0000x reference)
#include <cuda_runtime.h>
#include <math.h>

// ---------------------------------------------------------------------------
// WanRefAttnProcessor — fp32 baseline (round 0)
// B=1, T=4096, TR=1024, DIM=1536, H=12, DH=128
// ---------------------------------------------------------------------------

constexpr int T_   = 4096;
constexpr int TR_  = 1024;
constexpr int DIM_ = 1536;
constexpr int H_   = 12;
constexpr int DH_  = 128;
constexpr float EPS_ = 1e-6f;
constexpr float SCALE_ = 0.08838834764831845f; // 1/sqrt(128)

// Scratch (device globals — no allocation allowed)
__device__ float g_qlin [T_  * DIM_];
__device__ float g_klin [T_  * DIM_];
__device__ float g_vlin [T_  * DIM_];
__device__ float g_krlin[TR_ * DIM_];
__device__ float g_vrlin[TR_ * DIM_];
__device__ float g_qn   [T_  * DIM_];
__device__ float g_qr   [T_  * DIM_];
__device__ float g_kr   [T_  * DIM_];
__device__ float g_refk [TR_ * DIM_];
__device__ float g_attn [T_  * DIM_];

// ---------------------------------------------------------------------------
// SGEMM: C[M,1536] = A[M,1536] @ W[1536,1536] + bias
// 128x128 block tile, BK=8, 256 threads, 8x8 register tile per thread.
// ---------------------------------------------------------------------------
__global__ __launch_bounds__(256) void sgemm_bias_kernel(
    const float* __restrict__ A, const float* __restrict__ W,
    const float* __restrict__ bias, float* __restrict__ C, int M)
{
    const int N = DIM_, K = DIM_;
    __shared__ float As[8][128];
    __shared__ float Ws[8][128];

    const int bm = blockIdx.y * 128;
    const int bn = blockIdx.x * 128;
    const int tid = threadIdx.x;
    const int tx = tid & 15;
    const int ty = tid >> 4;

    const int arow = tid >> 1;
    const int acol = (tid & 1) * 4;
    const int wrow = tid >> 5;
    const int wcol = (tid & 31) * 4;

    const float* Aptr = A + (size_t)(bm + arow) * K + acol;
    const float* Wptr = W + (size_t)wrow * N + bn + wcol;

    float acc[8][8];
#pragma unroll
    for (int i = 0; i < 8; i++)
#pragma unroll
        for (int j = 0; j < 8; j++) acc[i][j] = 0.f;

    for (int k0 = 0; k0 < K; k0 += 8) {
        float4 av = *(const float4*)(Aptr + k0);
        float4 wv = *(const float4*)(Wptr + (size_t)k0 * N);
        As[acol + 0][arow] = av.x;
        As[acol + 1][arow] = av.y;
        As[acol + 2][arow] = av.z;
        As[acol + 3][arow] = av.w;
        *(float4*)&Ws[wrow][wcol] = wv;
        __syncthreads();

#pragma unroll
        for (int kk = 0; kk < 8; kk++) {
            float4 a0 = *(const float4*)&As[kk][ty * 8];
            float4 a1 = *(const float4*)&As[kk][ty * 8 + 4];
            float4 b0 = *(const float4*)&Ws[kk][tx * 8];
            float4 b1 = *(const float4*)&Ws[kk][tx * 8 + 4];
            float a[8] = {a0.x, a0.y, a0.z, a0.w, a1.x, a1.y, a1.z, a1.w};
            float b[8] = {b0.x, b0.y, b0.z, b0.w, b1.x, b1.y, b1.z, b1.w};
#pragma unroll
            for (int i = 0; i < 8; i++)
#pragma unroll
                for (int j = 0; j < 8; j++)
                    acc[i][j] = fmaf(a[i], b[j], acc[i][j]);
        }
        __syncthreads();
    }

#pragma unroll
    for (int i = 0; i < 8; i++) {
        const size_t row = (size_t)(bm + ty * 8 + i);
#pragma unroll
        for (int j = 0; j < 8; j += 4) {
            float4 o;
            o.x = acc[i][j + 0] + bias[bn + tx * 8 + j + 0];
            o.y = acc[i][j + 1] + bias[bn + tx * 8 + j + 1];
            o.z = acc[i][j + 2] + bias[bn + tx * 8 + j + 2];
            o.w = acc[i][j + 3] + bias[bn + tx * 8 + j + 3];
            *(float4*)&C[row * N + bn + tx * 8 + j] = o;
        }
    }
}

// ---------------------------------------------------------------------------
// RMSNorm (+ optional RoPE). One block per row, 384 threads x float4.
// outN: normalized (may be null).  outR: roped(normalized) (may be null).
// ---------------------------------------------------------------------------
__global__ __launch_bounds__(384) void norm_rope_kernel(
    const float* __restrict__ X, const float* __restrict__ g,
    const float* __restrict__ rc, const float* __restrict__ rs,
    float* __restrict__ outN, float* __restrict__ outR)
{
    const int row = blockIdx.x;
    const int tid = threadIdx.x;

    float4 v = ((const float4*)(X + (size_t)row * DIM_))[tid];
    float ss = v.x * v.x + v.y * v.y + v.z * v.z + v.w * v.w;

    __shared__ float red[12];
#pragma unroll
    for (int off = 16; off > 0; off >>= 1)
        ss += __shfl_xor_sync(0xffffffffu, ss, off);
    if ((tid & 31) == 0) red[tid >> 5] = ss;
    __syncthreads();
    float tot = 0.f;
#pragma unroll
    for (int i = 0; i < 12; i++) tot += red[i];

    const float inv = rsqrtf(tot * (1.f / (float)DIM_) + EPS_);

    float4 gg = ((const float4*)g)[tid];
    const float n0 = v.x * inv * gg.x;
    const float n1 = v.y * inv * gg.y;
    const float n2 = v.z * inv * gg.z;
    const float n3 = v.w * inv * gg.w;

    if (outN) {
        float4 o = {n0, n1, n2, n3};
        ((float4*)(outN + (size_t)row * DIM_))[tid] = o;
    }
    if (outR) {
        // within-head pair index: d = tid*4, e = d % 128, p = e/2
        const int p = (tid * 2) & 63;
        const float c0 = rc[row * 64 + p],     s0 = rs[row * 64 + p];
        const float c1 = rc[row * 64 + p + 1], s1 = rs[row * 64 + p + 1];
        float4 o;
        o.x = n0 * c0 - n1 * s0;
        o.y = n0 * s0 + n1 * c0;
        o.z = n2 * c1 - n3 * s1;
        o.w = n2 * s1 + n3 * c1;
        ((float4*)(outR + (size_t)row * DIM_))[tid] = o;
    }
}

// ---------------------------------------------------------------------------
// Flash attention fp32. Block = (64 queries) x (1 head). 256 threads.
// Q/K/V/O all laid out [rows, 1536] with head column offset h*128.
// Q pre-scaled by 1/sqrt(DH) on load. Online softmax, 64-key tiles.
// ---------------------------------------------------------------------------
__global__ __launch_bounds__(256) void flash_attn_kernel(
    const float* __restrict__ Q, const float* __restrict__ K,
    const float* __restrict__ V, float* __restrict__ O,
    int Tk, int addOut)
{
    extern __shared__ float sm[];
    float* sQ  = sm;               // [64][128]
    float* sKT = sQ + 64 * 128;    // [128][64]  (dim-major)
    float* sV  = sKT + 128 * 64;   // [64][128]
    float* sS  = sV + 64 * 128;    // [64][65]   padded: conflict-free softmax
    float* sM  = sS + 64 * 65;     // [64]
    float* sL  = sM + 64;          // [64]
    float* sA  = sL + 64;          // [64]

    const int tid = threadIdx.x;
    const int tx = tid & 15;
    const int ty = tid >> 4;
    const int h = blockIdx.y;
    const int qb = blockIdx.x * 64;
    const int hoff = h * DH_;

    // Load Q tile (scaled)
    {
        const int r  = tid >> 2;
        const int cb = (tid & 3) * 32;
        const float4* src = (const float4*)(Q + (size_t)(qb + r) * DIM_ + hoff + cb);
        float4* dst = (float4*)(sQ + r * 128 + cb);
#pragma unroll
        for (int u = 0; u < 8; u++) {
            float4 q = src[u];
            q.x *= SCALE_; q.y *= SCALE_; q.z *= SCALE_; q.w *= SCALE_;
            dst[u] = q;
        }
    }
    if (tid < 64) { sM[tid] = -1e30f; sL[tid] = 0.f; }

    float acc[4][8];
#pragma unroll
    for (int i = 0; i < 4; i++)
#pragma unroll
        for (int j = 0; j < 8; j++) acc[i][j] = 0.f;

    __syncthreads();

    for (int kb = 0; kb < Tk; kb += 64) {
        // Load K (transposed into sKT) and V tiles
        {
            const int r  = tid >> 2;
            const int cb = (tid & 3) * 32;
            const float4* ksrc = (const float4*)(K + (size_t)(kb + r) * DIM_ + hoff + cb);
            const float4* vsrc = (const float4*)(V + (size_t)(kb + r) * DIM_ + hoff + cb);
            float4* vdst = (float4*)(sV + r * 128 + cb);
#pragma unroll
            for (int u = 0; u < 8; u++) {
                float4 kv = ksrc[u];
                const int d = cb + u * 4;
                sKT[(d + 0) * 64 + r] = kv.x;
                sKT[(d + 1) * 64 + r] = kv.y;
                sKT[(d + 2) * 64 + r] = kv.z;
                sKT[(d + 3) * 64 + r] = kv.w;
                vdst[u] = vsrc[u];
            }
        }
        __syncthreads();

        // S = Qs @ K^T : each thread computes 4x4 of the 64x64 tile
        {
            float s[4][4];
#pragma unroll
            for (int i = 0; i < 4; i++)
#pragma unroll
                for (int j = 0; j < 4; j++) s[i][j] = 0.f;

            for (int d = 0; d < 128; d++) {
                float4 kv = *(const float4*)&sKT[d * 64 + tx * 4];
                float q[4];
#pragma unroll
                for (int i = 0; i < 4; i++) q[i] = sQ[(ty * 4 + i) * 128 + d];
                float kvv[4] = {kv.x, kv.y, kv.z, kv.w};
#pragma unroll
                for (int i = 0; i < 4; i++)
#pragma unroll
                    for (int j = 0; j < 4; j++)
                        s[i][j] = fmaf(q[i], kvv[j], s[i][j]);
            }
#pragma unroll
            for (int i = 0; i < 4; i++)
#pragma unroll
                for (int j = 0; j < 4; j++)
                    sS[(ty * 4 + i) * 65 + tx * 4 + j] = s[i][j];
        }
        __syncthreads();

        // Online softmax per row (threads 0..63 each own one row)
        if (tid < 64) {
            float* srow = sS + tid * 65;
            const float mo = sM[tid];
            float mt = mo;
#pragma unroll 8
            for (int j = 0; j < 64; j++) mt = fmaxf(mt, srow[j]);
            float lsum = 0.f;
#pragma unroll 8
            for (int j = 0; j < 64; j++) {
                const float p = __expf(srow[j] - mt);
                srow[j] = p;
                lsum += p;
            }
            const float alpha = __expf(mo - mt);
            sM[tid] = mt;
            sL[tid] = sL[tid] * alpha + lsum;
            sA[tid] = alpha;
        }
        __syncthreads();

        // Rescale accumulators, then O += P @ V
        {
            float al[4];
#pragma unroll
            for (int i = 0; i < 4; i++) al[i] = sA[ty * 4 + i];
#pragma unroll
            for (int i = 0; i < 4; i++)
#pragma unroll
                for (int j = 0; j < 8; j++) acc[i][j] *= al[i];

            for (int kk = 0; kk < 64; kk++) {
                float p[4];
#pragma unroll
                for (int i = 0; i < 4; i++) p[i] = sS[(ty * 4 + i) * 65 + kk];
                float4 v0 = *(const float4*)&sV[kk * 128 + tx * 8];
                float4 v1 = *(const float4*)&sV[kk * 128 + tx * 8 + 4];
                float vv[8] = {v0.x, v0.y, v0.z, v0.w, v1.x, v1.y, v1.z, v1.w};
#pragma unroll
                for (int i = 0; i < 4; i++)
#pragma unroll
                    for (int j = 0; j < 8; j++)
                        acc[i][j] = fmaf(p[i], vv[j], acc[i][j]);
            }
        }
        __syncthreads();
    }

    // Epilogue: O = acc / l  (+ previous O when accumulating ref attention)
#pragma unroll
    for (int i = 0; i < 4; i++) {
        const float invl = 1.f / sL[ty * 4 + i];
        const size_t base = (size_t)(qb + ty * 4 + i) * DIM_ + hoff + tx * 8;
#pragma unroll
        for (int j = 0; j < 8; j++) {
            float v = acc[i][j] * invl;
            if (addOut) v += O[base + j];
            O[base + j] = v;
        }
    }
}

// ---------------------------------------------------------------------------
// Launch
// ---------------------------------------------------------------------------
extern "C" void kernel_launch(void* const* d_in, const int* in_sizes, int n_in,
                              void* d_out, int out_size)
{
    (void)in_sizes; (void)n_in; (void)out_size;
    const float* hs  = (const float*)d_in[0];
    const float* rhs = (const float*)d_in[1];
    const float* rc  = (const float*)d_in[2];
    const float* rs  = (const float*)d_in[3];
    const float* Wq  = (const float*)d_in[4];
    const float* bq  = (const float*)d_in[5];
    const float* Wk  = (const float*)d_in[6];
    const float* bk  = (const float*)d_in[7];
    const float* Wv  = (const float*)d_in[8];
    const float* bv  = (const float*)d_in[9];
    const float* Wkr = (const float*)d_in[10];
    const float* bkr = (const float*)d_in[11];
    const float* Wvr = (const float*)d_in[12];
    const float* bvr = (const float*)d_in[13];
    const float* Wo  = (const float*)d_in[14];
    const float* bo  = (const float*)d_in[15];
    const float* gq  = (const float*)d_in[16];
    const float* gk  = (const float*)d_in[17];
    float* out = (float*)d_out;

    float *qlin, *klin, *vlin, *krlin, *vrlin, *qn, *qr, *kr, *refk, *attn;
    cudaGetSymbolAddress((void**)&qlin,  g_qlin);
    cudaGetSymbolAddress((void**)&klin,  g_klin);
    cudaGetSymbolAddress((void**)&vlin,  g_vlin);
    cudaGetSymbolAddress((void**)&krlin, g_krlin);
    cudaGetSymbolAddress((void**)&vrlin, g_vrlin);
    cudaGetSymbolAddress((void**)&qn,    g_qn);
    cudaGetSymbolAddress((void**)&qr,    g_qr);
    cudaGetSymbolAddress((void**)&kr,    g_kr);
    cudaGetSymbolAddress((void**)&refk,  g_refk);
    cudaGetSymbolAddress((void**)&attn,  g_attn);

    const dim3 gT (DIM_ / 128, T_  / 128);
    const dim3 gTR(DIM_ / 128, TR_ / 128);

    // Projections
    sgemm_bias_kernel<<<gT, 256>>>(hs,  Wq,  bq,  qlin,  T_);
    sgemm_bias_kernel<<<gT, 256>>>(hs,  Wk,  bk,  klin,  T_);
    sgemm_bias_kernel<<<gT, 256>>>(hs,  Wv,  bv,  vlin,  T_);
    sgemm_bias_kernel<<<gTR, 256>>>(rhs, Wkr, bkr, krlin, TR_);
    sgemm_bias_kernel<<<gTR, 256>>>(rhs, Wvr, bvr, vrlin, TR_);

    // RMSNorm + RoPE
    norm_rope_kernel<<<T_,  384>>>(qlin,  gq, rc, rs, qn,   qr);      // qn (ref_q) + roped q
    norm_rope_kernel<<<T_,  384>>>(klin,  gk, rc, rs, nullptr, kr);   // roped k
    norm_rope_kernel<<<TR_, 384>>>(krlin, gk, rc, rs, refk, nullptr); // ref_k

    // Attention (main writes, ref accumulates)
    const int fa_smem = (64 * 128 * 3 + 64 * 65 + 3 * 64) * (int)sizeof(float);
    cudaFuncSetAttribute(flash_attn_kernel,
                         cudaFuncAttributeMaxDynamicSharedMemorySize, fa_smem);
    const dim3 ga(T_ / 64, H_);
    flash_attn_kernel<<<ga, 256, fa_smem>>>(qr, kr,   vlin,  attn, T_,  0);
    flash_attn_kernel<<<ga, 256, fa_smem>>>(qn, refk, vrlin, attn, TR_, 1);

    // Output projection
    sgemm_bias_kernel<<<gT, 256>>>(attn, Wo, bo, out, T_);
}

// round 2
// speedup vs baseline: 1.0132x; 1.0132x over previous
#include <cuda_runtime.h>
#include <math.h>

// ---------------------------------------------------------------------------
// WanRefAttnProcessor — fp32 baseline (round 0)
// B=1, T=4096, TR=1024, DIM=1536, H=12, DH=128
// ---------------------------------------------------------------------------

constexpr int T_   = 4096;
constexpr int TR_  = 1024;
constexpr int DIM_ = 1536;
constexpr int H_   = 12;
constexpr int DH_  = 128;
constexpr float EPS_ = 1e-6f;
constexpr float SCALE_ = 0.08838834764831845f; // 1/sqrt(128)

// Scratch (device globals — no allocation allowed)
__device__ float g_qlin [T_  * DIM_];
__device__ float g_klin [T_  * DIM_];
__device__ float g_vlin [T_  * DIM_];
__device__ float g_krlin[TR_ * DIM_];
__device__ float g_vrlin[TR_ * DIM_];
__device__ float g_qn   [T_  * DIM_];
__device__ float g_qr   [T_  * DIM_];
__device__ float g_kr   [T_  * DIM_];
__device__ float g_refk [TR_ * DIM_];
__device__ float g_attn [T_  * DIM_];

// ---------------------------------------------------------------------------
// SGEMM: C[M,1536] = A[M,1536] @ W[1536,1536] + bias
// 128x128 block tile, BK=8, 256 threads, 8x8 register tile per thread.
// ---------------------------------------------------------------------------
__global__ __launch_bounds__(256) void sgemm_bias_kernel(
    const float* __restrict__ A, const float* __restrict__ W,
    const float* __restrict__ bias, float* __restrict__ C, int M)
{
    const int N = DIM_, K = DIM_;
    __shared__ float As[8][128];
    __shared__ float Ws[8][128];

    const int bm = blockIdx.y * 128;
    const int bn = blockIdx.x * 128;
    const int tid = threadIdx.x;
    const int tx = tid & 15;
    const int ty = tid >> 4;

    const int arow = tid >> 1;
    const int acol = (tid & 1) * 4;
    const int wrow = tid >> 5;
    const int wcol = (tid & 31) * 4;

    const float* Aptr = A + (size_t)(bm + arow) * K + acol;
    const float* Wptr = W + (size_t)wrow * N + bn + wcol;

    float acc[8][8];
#pragma unroll
    for (int i = 0; i < 8; i++)
#pragma unroll
        for (int j = 0; j < 8; j++) acc[i][j] = 0.f;

    for (int k0 = 0; k0 < K; k0 += 8) {
        float4 av = *(const float4*)(Aptr + k0);
        float4 wv = *(const float4*)(Wptr + (size_t)k0 * N);
        As[acol + 0][arow] = av.x;
        As[acol + 1][arow] = av.y;
        As[acol + 2][arow] = av.z;
        As[acol + 3][arow] = av.w;
        *(float4*)&Ws[wrow][wcol] = wv;
        __syncthreads();

#pragma unroll
        for (int kk = 0; kk < 8; kk++) {
            float4 a0 = *(const float4*)&As[kk][ty * 8];
            float4 a1 = *(const float4*)&As[kk][ty * 8 + 4];
            float4 b0 = *(const float4*)&Ws[kk][tx * 8];
            float4 b1 = *(const float4*)&Ws[kk][tx * 8 + 4];
            float a[8] = {a0.x, a0.y, a0.z, a0.w, a1.x, a1.y, a1.z, a1.w};
            float b[8] = {b0.x, b0.y, b0.z, b0.w, b1.x, b1.y, b1.z, b1.w};
#pragma unroll
            for (int i = 0; i < 8; i++)
#pragma unroll
                for (int j = 0; j < 8; j++)
                    acc[i][j] = fmaf(a[i], b[j], acc[i][j]);
        }
        __syncthreads();
    }

#pragma unroll
    for (int i = 0; i < 8; i++) {
        const size_t row = (size_t)(bm + ty * 8 + i);
#pragma unroll
        for (int j = 0; j < 8; j += 4) {
            float4 o;
            o.x = acc[i][j + 0] + bias[bn + tx * 8 + j + 0];
            o.y = acc[i][j + 1] + bias[bn + tx * 8 + j + 1];
            o.z = acc[i][j + 2] + bias[bn + tx * 8 + j + 2];
            o.w = acc[i][j + 3] + bias[bn + tx * 8 + j + 3];
            *(float4*)&C[row * N + bn + tx * 8 + j] = o;
        }
    }
}

// ---------------------------------------------------------------------------
// RMSNorm (+ optional RoPE). One block per row, 384 threads x float4.
// outN: normalized (may be null).  outR: roped(normalized) (may be null).
// ---------------------------------------------------------------------------
__global__ __launch_bounds__(384) void norm_rope_kernel(
    const float* __restrict__ X, const float* __restrict__ g,
    const float* __restrict__ rc, const float* __restrict__ rs,
    float* __restrict__ outN, float* __restrict__ outR)
{
    const int row = blockIdx.x;
    const int tid = threadIdx.x;

    float4 v = ((const float4*)(X + (size_t)row * DIM_))[tid];
    float ss = v.x * v.x + v.y * v.y + v.z * v.z + v.w * v.w;

    __shared__ float red[12];
#pragma unroll
    for (int off = 16; off > 0; off >>= 1)
        ss += __shfl_xor_sync(0xffffffffu, ss, off);
    if ((tid & 31) == 0) red[tid >> 5] = ss;
    __syncthreads();
    float tot = 0.f;
#pragma unroll
    for (int i = 0; i < 12; i++) tot += red[i];

    const float inv = rsqrtf(tot * (1.f / (float)DIM_) + EPS_);

    float4 gg = ((const float4*)g)[tid];
    const float n0 = v.x * inv * gg.x;
    const float n1 = v.y * inv * gg.y;
    const float n2 = v.z * inv * gg.z;
    const float n3 = v.w * inv * gg.w;

    if (outN) {
        float4 o = {n0, n1, n2, n3};
        ((float4*)(outN + (size_t)row * DIM_))[tid] = o;
    }
    if (outR) {
        // within-head pair index: d = tid*4, e = d % 128, p = e/2
        const int p = (tid * 2) & 63;
        const float c0 = rc[row * 64 + p],     s0 = rs[row * 64 + p];
        const float c1 = rc[row * 64 + p + 1], s1 = rs[row * 64 + p + 1];
        float4 o;
        o.x = n0 * c0 - n1 * s0;
        o.y = n0 * s0 + n1 * c0;
        o.z = n2 * c1 - n3 * s1;
        o.w = n2 * s1 + n3 * c1;
        ((float4*)(outR + (size_t)row * DIM_))[tid] = o;
    }
}

// ---------------------------------------------------------------------------
// Flash attention fp32. Block = (64 queries) x (1 head). 256 threads.
// Q/K/V/O all laid out [rows, 1536] with head column offset h*128.
// Q pre-scaled by 1/sqrt(DH) on load. Online softmax, 64-key tiles.
// ---------------------------------------------------------------------------
__global__ __launch_bounds__(256) void flash_attn_kernel(
    const float* __restrict__ Q, const float* __restrict__ K,
    const float* __restrict__ V, float* __restrict__ O,
    int Tk, int addOut)
{
    extern __shared__ float sm[];
    float* sQ  = sm;               // [64][128]
    float* sKT = sQ + 64 * 128;    // [128][64]  (dim-major)
    float* sV  = sKT + 128 * 64;   // [64][128]
    float* sS  = sV + 64 * 128;    // [64][65]   padded: conflict-free softmax
    float* sM  = sS + 64 * 65;     // [64]
    float* sL  = sM + 64;          // [64]
    float* sA  = sL + 64;          // [64]

    const int tid = threadIdx.x;
    const int tx = tid & 15;
    const int ty = tid >> 4;
    const int h = blockIdx.y;
    const int qb = blockIdx.x * 64;
    const int hoff = h * DH_;

    // Load Q tile (scaled)
    {
        const int r  = tid >> 2;
        const int cb = (tid & 3) * 32;
        const float4* src = (const float4*)(Q + (size_t)(qb + r) * DIM_ + hoff + cb);
        float4* dst = (float4*)(sQ + r * 128 + cb);
#pragma unroll
        for (int u = 0; u < 8; u++) {
            float4 q = src[u];
            q.x *= SCALE_; q.y *= SCALE_; q.z *= SCALE_; q.w *= SCALE_;
            dst[u] = q;
        }
    }
    if (tid < 64) { sM[tid] = -1e30f; sL[tid] = 0.f; }

    float acc[4][8];
#pragma unroll
    for (int i = 0; i < 4; i++)
#pragma unroll
        for (int j = 0; j < 8; j++) acc[i][j] = 0.f;

    __syncthreads();

    for (int kb = 0; kb < Tk; kb += 64) {
        // Load K (transposed into sKT) and V tiles
        {
            const int r  = tid >> 2;
            const int cb = (tid & 3) * 32;
            const float4* ksrc = (const float4*)(K + (size_t)(kb + r) * DIM_ + hoff + cb);
            const float4* vsrc = (const float4*)(V + (size_t)(kb + r) * DIM_ + hoff + cb);
            float4* vdst = (float4*)(sV + r * 128 + cb);
#pragma unroll
            for (int u = 0; u < 8; u++) {
                float4 kv = ksrc[u];
                const int d = cb + u * 4;
                sKT[(d + 0) * 64 + r] = kv.x;
                sKT[(d + 1) * 64 + r] = kv.y;
                sKT[(d + 2) * 64 + r] = kv.z;
                sKT[(d + 3) * 64 + r] = kv.w;
                vdst[u] = vsrc[u];
            }
        }
        __syncthreads();

        // S = Qs @ K^T : each thread computes 4x4 of the 64x64 tile
        {
            float s[4][4];
#pragma unroll
            for (int i = 0; i < 4; i++)
#pragma unroll
                for (int j = 0; j < 4; j++) s[i][j] = 0.f;

            for (int d = 0; d < 128; d++) {
                float4 kv = *(const float4*)&sKT[d * 64 + tx * 4];
                float q[4];
#pragma unroll
                for (int i = 0; i < 4; i++) q[i] = sQ[(ty * 4 + i) * 128 + d];
                float kvv[4] = {kv.x, kv.y, kv.z, kv.w};
#pragma unroll
                for (int i = 0; i < 4; i++)
#pragma unroll
                    for (int j = 0; j < 4; j++)
                        s[i][j] = fmaf(q[i], kvv[j], s[i][j]);
            }
#pragma unroll
            for (int i = 0; i < 4; i++)
#pragma unroll
                for (int j = 0; j < 4; j++)
                    sS[(ty * 4 + i) * 65 + tx * 4 + j] = s[i][j];
        }
        __syncthreads();

        // Online softmax per row (threads 0..63 each own one row)
        if (tid < 64) {
            float* srow = sS + tid * 65;
            const float mo = sM[tid];
            float mt = mo;
#pragma unroll 8
            for (int j = 0; j < 64; j++) mt = fmaxf(mt, srow[j]);
            float lsum = 0.f;
#pragma unroll 8
            for (int j = 0; j < 64; j++) {
                const float p = __expf(srow[j] - mt);
                srow[j] = p;
                lsum += p;
            }
            const float alpha = __expf(mo - mt);
            sM[tid] = mt;
            sL[tid] = sL[tid] * alpha + lsum;
            sA[tid] = alpha;
        }
        __syncthreads();

        // Rescale accumulators, then O += P @ V
        {
            float al[4];
#pragma unroll
            for (int i = 0; i < 4; i++) al[i] = sA[ty * 4 + i];
#pragma unroll
            for (int i = 0; i < 4; i++)
#pragma unroll
                for (int j = 0; j < 8; j++) acc[i][j] *= al[i];

            for (int kk = 0; kk < 64; kk++) {
                float p[4];
#pragma unroll
                for (int i = 0; i < 4; i++) p[i] = sS[(ty * 4 + i) * 65 + kk];
                float4 v0 = *(const float4*)&sV[kk * 128 + tx * 8];
                float4 v1 = *(const float4*)&sV[kk * 128 + tx * 8 + 4];
                float vv[8] = {v0.x, v0.y, v0.z, v0.w, v1.x, v1.y, v1.z, v1.w};
#pragma unroll
                for (int i = 0; i < 4; i++)
#pragma unroll
                    for (int j = 0; j < 8; j++)
                        acc[i][j] = fmaf(p[i], vv[j], acc[i][j]);
            }
        }
        __syncthreads();
    }

    // Epilogue: O = acc / l  (+ previous O when accumulating ref attention)
#pragma unroll
    for (int i = 0; i < 4; i++) {
        const float invl = 1.f / sL[ty * 4 + i];
        const size_t base = (size_t)(qb + ty * 4 + i) * DIM_ + hoff + tx * 8;
#pragma unroll
        for (int j = 0; j < 8; j++) {
            float v = acc[i][j] * invl;
            if (addOut) v += O[base + j];
            O[base + j] = v;
        }
    }
}

// ---------------------------------------------------------------------------
// Launch
// ---------------------------------------------------------------------------
extern "C" void kernel_launch(void* const* d_in, const int* in_sizes, int n_in,
                              void* d_out, int out_size)
{
    (void)in_sizes; (void)n_in; (void)out_size;
    const float* hs  = (const float*)d_in[0];
    const float* rhs = (const float*)d_in[1];
    const float* rc  = (const float*)d_in[2];
    const float* rs  = (const float*)d_in[3];
    const float* Wq  = (const float*)d_in[4];
    const float* bq  = (const float*)d_in[5];
    const float* Wk  = (const float*)d_in[6];
    const float* bk  = (const float*)d_in[7];
    const float* Wv  = (const float*)d_in[8];
    const float* bv  = (const float*)d_in[9];
    const float* Wkr = (const float*)d_in[10];
    const float* bkr = (const float*)d_in[11];
    const float* Wvr = (const float*)d_in[12];
    const float* bvr = (const float*)d_in[13];
    const float* Wo  = (const float*)d_in[14];
    const float* bo  = (const float*)d_in[15];
    const float* gq  = (const float*)d_in[16];
    const float* gk  = (const float*)d_in[17];
    float* out = (float*)d_out;

    float *qlin, *klin, *vlin, *krlin, *vrlin, *qn, *qr, *kr, *refk, *attn;
    cudaGetSymbolAddress((void**)&qlin,  g_qlin);
    cudaGetSymbolAddress((void**)&klin,  g_klin);
    cudaGetSymbolAddress((void**)&vlin,  g_vlin);
    cudaGetSymbolAddress((void**)&krlin, g_krlin);
    cudaGetSymbolAddress((void**)&vrlin, g_vrlin);
    cudaGetSymbolAddress((void**)&qn,    g_qn);
    cudaGetSymbolAddress((void**)&qr,    g_qr);
    cudaGetSymbolAddress((void**)&kr,    g_kr);
    cudaGetSymbolAddress((void**)&refk,  g_refk);
    cudaGetSymbolAddress((void**)&attn,  g_attn);

    const dim3 gT (DIM_ / 128, T_  / 128);
    const dim3 gTR(DIM_ / 128, TR_ / 128);

    // Projections
    sgemm_bias_kernel<<<gT, 256>>>(hs,  Wq,  bq,  qlin,  T_);
    sgemm_bias_kernel<<<gT, 256>>>(hs,  Wk,  bk,  klin,  T_);
    sgemm_bias_kernel<<<gT, 256>>>(hs,  Wv,  bv,  vlin,  T_);
    sgemm_bias_kernel<<<gTR, 256>>>(rhs, Wkr, bkr, krlin, TR_);
    sgemm_bias_kernel<<<gTR, 256>>>(rhs, Wvr, bvr, vrlin, TR_);

    // RMSNorm + RoPE
    norm_rope_kernel<<<T_,  384>>>(qlin,  gq, rc, rs, qn,   qr);      // qn (ref_q) + roped q
    norm_rope_kernel<<<T_,  384>>>(klin,  gk, rc, rs, nullptr, kr);   // roped k
    norm_rope_kernel<<<TR_, 384>>>(krlin, gk, rc, rs, refk, nullptr); // ref_k

    // Attention (main writes, ref accumulates)
    const int fa_smem = (64 * 128 * 3 + 64 * 65 + 3 * 64) * (int)sizeof(float);
    cudaFuncSetAttribute(flash_attn_kernel,
                         cudaFuncAttributeMaxDynamicSharedMemorySize, fa_smem);
    const dim3 ga(T_ / 64, H_);
    flash_attn_kernel<<<ga, 256, fa_smem>>>(qr, kr,   vlin,  attn, T_,  0);
    flash_attn_kernel<<<ga, 256, fa_smem>>>(qn, refk, vrlin, attn, TR_, 1);

    // Output projection
    sgemm_bias_kernel<<<gT, 256>>>(attn, Wo, bo, out, T_);
}